// round 10
// baseline (speedup 1.0000x reference)
#include <cuda_runtime.h>

// Problem constants (fixed by the dataset instance)
#define BB 8
#define CC_TOT 32
#define HH 256
#define WW 512
#define WR 2048
#define DD 48
#define DHALF 24               // disparities per CTA
#define CPC 2                  // channels per staged buffer
#define NIT (CC_TOT / CPC)     // 16 pipeline iterations
#define NSTG 3                 // cp.async pipeline stages
#define TPB 128                // threads per CTA; each owns 2 adjacent pixels
#define WTILE 256              // w positions per CTA
#define NF4T 262               // staged f4 per channel row window
#define ROWL4 264              // row stride (f4)
#define SWZ(i) ((i) ^ (((i) >> 3) & 1))   // bank-conflict swizzle on f4 index
#define ABSMASK 0x7FFFFFFF7FFFFFFFULL
#define NEG1P   0xBF800000BF800000ULL      // packed (-1.0f, -1.0f)

// cost[b,d,h,w] = sum_c | L[b,c,h,w] - R[b,c,h,4w-d] |, R col<0 treated as 0.
// Thread owns pixels w0=wbase+2*tid, w0+1; union window f4 2*tid+j, j=0..7.
// pixel0: a = 24-4j-e; pixel1: a1 = 28-4j-e; valid iff in [0,24). Packed f32x2
// accumulators, one per unique (j, e-pair); dummy lanes never read.
// (Mapping + packing verified R5-R9, rel_err = 0.)
// R10: 6 CTAs/SM. Register cuts vs R9: 2-f4 window chunks (live 8 regs) and
// L prefetch depth 1 (one lp buffer).

__device__ __forceinline__ void cp_async16(unsigned dst, const void* src) {
    asm volatile("cp.async.cg.shared.global [%0], [%1], 16;\n"
                 :: "r"(dst), "l"(src));
}
__device__ __forceinline__ unsigned long long pack2(float lo, float hi) {
    unsigned long long r;
    asm("mov.b64 %0, {%1, %2};" : "=l"(r) : "f"(lo), "f"(hi));
    return r;
}
__device__ __forceinline__ void unpack2(unsigned long long v, float& lo, float& hi) {
    asm("mov.b64 {%0, %1}, %2;" : "=f"(lo), "=f"(hi) : "l"(v));
}
__device__ __forceinline__ unsigned long long fma2(unsigned long long a,
                                                   unsigned long long b,
                                                   unsigned long long c) {
    unsigned long long d;
    asm("fma.rn.f32x2 %0, %1, %2, %3;" : "=l"(d) : "l"(a), "l"(b), "l"(c));
    return d;
}
__device__ __forceinline__ unsigned long long add2(unsigned long long a,
                                                   unsigned long long b) {
    unsigned long long d;
    asm("add.rn.f32x2 %0, %1, %2;" : "=l"(d) : "l"(a), "l"(b));
    return d;
}
// acc += |lv2 - v2|  (packed, two lanes)
__device__ __forceinline__ void upd(unsigned long long& acc,
                                    unsigned long long v2,
                                    unsigned long long lv2,
                                    unsigned long long neg1) {
    unsigned long long t = fma2(v2, neg1, lv2);   // exact lv - v
    t &= ABSMASK;                                  // packed abs (2x LOP3, alu)
    acc = add2(acc, t);
}

__global__ __launch_bounds__(TPB, 6)
void build_volume2d_kernel(const float* __restrict__ L,
                           const float* __restrict__ R,
                           float* __restrict__ out) {
    __shared__ float4 s4[NSTG][CPC][ROWL4];   // 3*2*264*16 = 25344 B

    const int tid = threadIdx.x;
    const int g   = blockIdx.x & 1;        // d half
    const int wt  = blockIdx.x >> 1;       // w tile (0 or 1)
    const int h   = blockIdx.y;
    const int b   = blockIdx.z;
    const int k0  = 6 - 6 * g;
    const int wbase = wt * WTILE;
    const int w0  = wbase + 2 * tid;
    const int g4s = wbase + k0;            // global padded-f4 index of local li=0
    const int rcol0 = 4 * g4s - 48;        // R column of local f4 0, element 0
    const int nzero = (wt == 0) ? (12 - k0) : 0;   // pad-only f4s (g=0:6, g=1:12)

    // One-time zero of pad f4s (never touched by cp.async; disjoint addresses).
    if (tid < NSTG * CPC * 12) {
        int st = tid / (CPC * 12);
        int ch = (tid / 12) % CPC;
        int li = tid % 12;
        if (li < nzero) s4[st][ch][SWZ(li)] = make_float4(0.f, 0.f, 0.f, 0.f);
    }

    int idx[8];
#pragma unroll
    for (int j = 0; j < 8; j++) idx[j] = SWZ(2 * tid + j);

    // Packed accumulators (see header comment).
    unsigned long long p0h0[7], p0h1[6], p1h0[7], p1h1[6];
#pragma unroll
    for (int i = 0; i < 7; i++) { p0h0[i] = 0ull; p1h0[i] = 0ull; }
#pragma unroll
    for (int i = 0; i < 6; i++) { p0h1[i] = 0ull; p1h1[i] = 0ull; }

    const unsigned long long neg1 = NEG1P;

    const float* Lbh = L + ((size_t)b * CC_TOT * HH + h) * WW + w0;  // + c*HH*WW
    const float* Rbh = R + ((size_t)b * CC_TOT * HH + h) * WR;       // + c*HH*WR

    auto fill = [&](int st, int c0) {
#pragma unroll
        for (int base = 0; base < NF4T; base += TPB) {   // li = tid, +128, +256
            int li = base + tid;
            if (li < NF4T && li >= nzero) {
#pragma unroll
                for (int ch = 0; ch < CPC; ++ch) {
                    const float* src =
                        Rbh + (size_t)(c0 + ch) * HH * WR + (rcol0 + 4 * li);
                    cp_async16((unsigned)__cvta_generic_to_shared(
                                   &s4[st][ch][SWZ(li)]), src);
                }
            }
        }
    };
    auto loadL = [&](int c0, float2* dst) {
#pragma unroll
        for (int ch = 0; ch < CPC; ++ch)
            dst[ch] = __ldg(reinterpret_cast<const float2*>(
                                Lbh + (size_t)(c0 + ch) * HH * WW));
    };

    fill(0, 0);
    asm volatile("cp.async.commit_group;\n" ::: "memory");
    fill(1, CPC);
    asm volatile("cp.async.commit_group;\n" ::: "memory");
    float2 lp[CPC];
    loadL(0, lp);

    // Per-(j, f4) packed update; j compile-time after unroll.
    auto body = [&](int j, float4 v,
                    unsigned long long LV0, unsigned long long LV1) {
        unsigned long long v01 = pack2(v.x, v.y);
        unsigned long long v23 = pack2(v.z, v.w);
        if (j <= 6)           upd(p0h0[j],     v01, LV0, neg1);
        if (j <= 5)           upd(p0h1[j],     v23, LV0, neg1);
        if (j >= 1)           upd(p1h0[j - 1], v01, LV1, neg1);
        if (j >= 1 && j <= 6) upd(p1h1[j - 1], v23, LV1, neg1);
    };

    for (int it = 0; it < NIT; ++it) {
        const int st = it % NSTG;
        const int c0 = CPC * it;

        if (it < NIT - 1) {
            asm volatile("cp.async.wait_group 1;\n" ::: "memory");
        } else {
            asm volatile("cp.async.wait_group 0;\n" ::: "memory");
        }
        __syncthreads();   // slot st visible; all warps past consume(it-1)

        // Prefetch next iteration's L (depth 1) and stage chunk it+2.
        float2 lpn[CPC];
        if (it + 1 < NIT) loadL(c0 + CPC, lpn);
        if (it + 2 < NIT) {
            fill((it + 2) % NSTG, c0 + 2 * CPC);
            asm volatile("cp.async.commit_group;\n" ::: "memory");
        }

#pragma unroll
        for (int ch = 0; ch < CPC; ++ch) {
            const unsigned long long LV0 = pack2(lp[ch].x, lp[ch].x);
            const unsigned long long LV1 = pack2(lp[ch].y, lp[ch].y);
            const float4* row = s4[st][ch];

#pragma unroll
            for (int q = 0; q < 4; q++) {      // 4 chunks of 2 f4 (8 live regs)
                float4 va = row[idx[2 * q]];
                float4 vb = row[idx[2 * q + 1]];
                body(2 * q,     va, LV0, LV1);
                body(2 * q + 1, vb, LV0, LV1);
            }
        }
#pragma unroll
        for (int ch = 0; ch < CPC; ++ch) lp[ch] = lpn[ch];
    }

    // Unpack packed accumulators to per-disparity values (coverage verified R8).
    float acc0[DHALF], acc1[DHALF];
#pragma unroll
    for (int j = 0; j <= 6; j++) {
        float lo, hi;
        unpack2(p0h0[j], lo, hi);
        if (24 - 4 * j < DHALF) acc0[24 - 4 * j] = lo;
        if (23 - 4 * j >= 0)    acc0[23 - 4 * j] = hi;
    }
#pragma unroll
    for (int j = 0; j <= 5; j++) {
        float lo, hi;
        unpack2(p0h1[j], lo, hi);
        acc0[22 - 4 * j] = lo;
        acc0[21 - 4 * j] = hi;
    }
#pragma unroll
    for (int j = 1; j <= 7; j++) {
        float lo, hi;
        unpack2(p1h0[j - 1], lo, hi);
        if (28 - 4 * j < DHALF) acc1[28 - 4 * j] = lo;
        if (27 - 4 * j >= 0)    acc1[27 - 4 * j] = hi;
    }
#pragma unroll
    for (int j = 1; j <= 6; j++) {
        float lo, hi;
        unpack2(p1h1[j - 1], lo, hi);
        acc1[26 - 4 * j] = lo;
        acc1[25 - 4 * j] = hi;
    }

    // out[b, 24g + a, h, w0..w0+1] as float2 (coalesced per a).
    const size_t obase = (((size_t)b * DD + DHALF * g) * HH + h) * WW + w0;
#pragma unroll
    for (int a = 0; a < DHALF; a++) {
        *reinterpret_cast<float2*>(&out[obase + (size_t)a * HH * WW]) =
            make_float2(acc0[a], acc1[a]);
    }
}

extern "C" void kernel_launch(void* const* d_in, const int* in_sizes, int n_in,
                              void* d_out, int out_size) {
    const float* feat_l = (const float*)d_in[0];
    const float* feat_r = (const float*)d_in[1];
    float* out = (float*)d_out;

    dim3 grid(4, HH, BB);   // x = (wt<<1)|g : twin-g CTAs share R rows via L2
    build_volume2d_kernel<<<grid, TPB>>>(feat_l, feat_r, out);
}

// round 11
// speedup vs baseline: 1.0872x; 1.0872x over previous
#include <cuda_runtime.h>

// Problem constants (fixed by the dataset instance)
#define BB 8
#define CC_TOT 32
#define HH 256
#define WW 512
#define WR 2048
#define DD 48
#define DHALF 24               // disparities per CTA
#define CPC 2                  // channels per staged buffer
#define NIT (CC_TOT / CPC)     // 16 pipeline iterations
#define NSTG 3                 // cp.async pipeline stages (per warp)
#define TPB 128                // 4 warps; each warp owns 64 pixels (2/thread)
#define WTILE 256              // w positions per CTA
#define WF4 70                 // window f4 per warp per channel (64 px + 6)
#define WROW 72                // padded row stride (f4)
#define SWZ(i) ((i) ^ (((i) >> 3) & 1))   // bank-conflict swizzle on f4 index
#define ABSMASK 0x7FFFFFFF7FFFFFFFULL
#define NEG1P   0xBF800000BF800000ULL      // packed (-1.0f, -1.0f)

// cost[b,d,h,w] = sum_c | L[b,c,h,w] - R[b,c,h,4w-d] |, R col<0 treated as 0.
// Padded float index p = 4w + 48 - d; half g: pixel w reads padded f4
// [w+k0, w+k0+6], k0 = 6-6g. Thread owns pixels w0, w0+1; union window is
// 8 f4 starting at local index 2*lane. pixel0: a = 24-4j-e; pixel1:
// a1 = 28-4j-e; valid iff in [0,24). Packed f32x2 accumulators, one per
// unique (j, e-pair); dummy lanes never read. (All verified R5-R9.)
// R11: warp-private staging+consume pipelines. No __syncthreads in the main
// loop; per-warp cp.async groups + __syncwarp only.

__device__ __forceinline__ void cp_async16(unsigned dst, const void* src) {
    asm volatile("cp.async.cg.shared.global [%0], [%1], 16;\n"
                 :: "r"(dst), "l"(src));
}
__device__ __forceinline__ unsigned long long pack2(float lo, float hi) {
    unsigned long long r;
    asm("mov.b64 %0, {%1, %2};" : "=l"(r) : "f"(lo), "f"(hi));
    return r;
}
__device__ __forceinline__ void unpack2(unsigned long long v, float& lo, float& hi) {
    asm("mov.b64 {%0, %1}, %2;" : "=f"(lo), "=f"(hi) : "l"(v));
}
__device__ __forceinline__ unsigned long long fma2(unsigned long long a,
                                                   unsigned long long b,
                                                   unsigned long long c) {
    unsigned long long d;
    asm("fma.rn.f32x2 %0, %1, %2, %3;" : "=l"(d) : "l"(a), "l"(b), "l"(c));
    return d;
}
__device__ __forceinline__ unsigned long long add2(unsigned long long a,
                                                   unsigned long long b) {
    unsigned long long d;
    asm("add.rn.f32x2 %0, %1, %2;" : "=l"(d) : "l"(a), "l"(b));
    return d;
}
// acc += |lv2 - v2|  (packed, two lanes)
__device__ __forceinline__ void upd(unsigned long long& acc,
                                    unsigned long long v2,
                                    unsigned long long lv2,
                                    unsigned long long neg1) {
    unsigned long long t = fma2(v2, neg1, lv2);   // exact lv - v
    t &= ABSMASK;                                  // packed abs (2x LOP3, alu)
    acc = add2(acc, t);
}

__global__ __launch_bounds__(TPB, 5)
void build_volume2d_kernel(const float* __restrict__ L,
                           const float* __restrict__ R,
                           float* __restrict__ out) {
    // Per-warp private staging: [warp][stage][ch][f4]
    __shared__ float4 s4[4][NSTG][CPC][WROW];   // 4*3*2*72*16 = 27648 B

    const int lane = threadIdx.x & 31;
    const int wrp  = threadIdx.x >> 5;     // 0..3
    const int g    = blockIdx.x & 1;       // d half
    const int wt   = blockIdx.x >> 1;      // w tile (0 or 1)
    const int h    = blockIdx.y;
    const int b    = blockIdx.z;
    const int k0   = 6 - 6 * g;
    const int W0   = wt * WTILE + wrp * 64;      // first pixel of this warp
    const int w0   = W0 + 2 * lane;              // this thread's pixel 0
    const int rcol0 = 4 * (W0 + k0) - 48;        // R column of local f4 0, elem 0
    // local f4 li < nzero lie entirely in the zero pad (only warp 0 of wt=0)
    const int nzero = (wt == 0 && wrp == 0) ? (12 - k0) : 0;  // g=0:6, g=1:12

    // One-time zero of this warp's pad f4s (cp.async never writes li<nzero).
    if (nzero > 0) {
        for (int i = lane; i < NSTG * CPC * nzero; i += 32) {
            int st = i / (CPC * nzero);
            int ch = (i / nzero) % CPC;
            int li = i % nzero;
            s4[wrp][st][ch][SWZ(li)] = make_float4(0.f, 0.f, 0.f, 0.f);
        }
    }
    __syncwarp();

    int idx[8];
#pragma unroll
    for (int j = 0; j < 8; j++) idx[j] = SWZ(2 * lane + j);

    // Packed accumulators. p0h0[j]: pixel0 (a=24-4j, 23-4j), j=0..6.
    // p0h1[j]: pixel0 (22-4j, 21-4j), j=0..5. p1h0[j-1]: pixel1 (28-4j,27-4j),
    // j=1..7. p1h1[j-1]: pixel1 (26-4j, 25-4j), j=1..6. Dummies never read.
    unsigned long long p0h0[7], p0h1[6], p1h0[7], p1h1[6];
#pragma unroll
    for (int i = 0; i < 7; i++) { p0h0[i] = 0ull; p1h0[i] = 0ull; }
#pragma unroll
    for (int i = 0; i < 6; i++) { p0h1[i] = 0ull; p1h1[i] = 0ull; }

    const unsigned long long neg1 = NEG1P;

    const float* Lbh = L + ((size_t)b * CC_TOT * HH + h) * WW + w0;  // + c*HH*WW
    const float* Rbh = R + ((size_t)b * CC_TOT * HH + h) * WR;       // + c*HH*WR

    // Stage CPC channels of this warp's window into stage st.
    auto fill = [&](int st, int c0) {
#pragma unroll
        for (int ch = 0; ch < CPC; ++ch) {
            const float* src0 = Rbh + (size_t)(c0 + ch) * HH * WR + rcol0;
#pragma unroll
            for (int base = 0; base < WF4; base += 32) {   // li = lane, +32, +64
                int li = base + lane;
                if (li < WF4 && li >= nzero) {
                    cp_async16((unsigned)__cvta_generic_to_shared(
                                   &s4[wrp][st][ch][SWZ(li)]),
                               src0 + 4 * li);
                }
            }
        }
    };
    auto loadL = [&](int c0, float2* dst) {
#pragma unroll
        for (int ch = 0; ch < CPC; ++ch)
            dst[ch] = __ldg(reinterpret_cast<const float2*>(
                                Lbh + (size_t)(c0 + ch) * HH * WW));
    };

    fill(0, 0);
    asm volatile("cp.async.commit_group;\n" ::: "memory");
    fill(1, CPC);
    asm volatile("cp.async.commit_group;\n" ::: "memory");
    float2 lp0[CPC], lp1[CPC];
    loadL(0, lp0);
    loadL(CPC, lp1);

    // Per-(j, f4) packed update; j compile-time after unroll.
    auto body = [&](int j, float4 v,
                    unsigned long long LV0, unsigned long long LV1) {
        unsigned long long v01 = pack2(v.x, v.y);
        unsigned long long v23 = pack2(v.z, v.w);
        if (j <= 6)           upd(p0h0[j],     v01, LV0, neg1);
        if (j <= 5)           upd(p0h1[j],     v23, LV0, neg1);
        if (j >= 1)           upd(p1h0[j - 1], v01, LV1, neg1);
        if (j >= 1 && j <= 6) upd(p1h1[j - 1], v23, LV1, neg1);
    };

    for (int it = 0; it < NIT; ++it) {
        const int st = it % NSTG;
        const int c0 = CPC * it;

        if (it < NIT - 1) {
            asm volatile("cp.async.wait_group 1;\n" ::: "memory");
        } else {
            asm volatile("cp.async.wait_group 0;\n" ::: "memory");
        }
        __syncwarp();   // cross-lane visibility of this warp's staged data

        // Prefetch L (depth 2) and stage chunk it+2 into slot consumed at it-1
        // (this warp finished reading it at the end of iteration it-1).
        float2 lp2[CPC];
        if (it + 2 < NIT) {
            loadL(c0 + 2 * CPC, lp2);
            fill((it + 2) % NSTG, c0 + 2 * CPC);
            asm volatile("cp.async.commit_group;\n" ::: "memory");
        }

#pragma unroll
        for (int ch = 0; ch < CPC; ++ch) {
            const unsigned long long LV0 = pack2(lp0[ch].x, lp0[ch].x);
            const unsigned long long LV1 = pack2(lp0[ch].y, lp0[ch].y);
            const float4* row = s4[wrp][st][ch];

            // Two chunks of 4 f4 (keeps LDS MLP=4, regs bounded) — R9 layout.
            float4 va[4];
#pragma unroll
            for (int q = 0; q < 4; q++) va[q] = row[idx[q]];
#pragma unroll
            for (int j = 0; j < 4; j++) body(j, va[j], LV0, LV1);

            float4 vb[4];
#pragma unroll
            for (int q = 0; q < 4; q++) vb[q] = row[idx[4 + q]];
#pragma unroll
            for (int j = 4; j < 8; j++) body(j, vb[j - 4], LV0, LV1);
        }
#pragma unroll
        for (int ch = 0; ch < CPC; ++ch) { lp0[ch] = lp1[ch]; lp1[ch] = lp2[ch]; }

        __syncwarp();   // all lanes done with slot st before this warp refills
    }

    // Unpack packed accumulators to per-disparity values (coverage verified R8).
    float acc0[DHALF], acc1[DHALF];
#pragma unroll
    for (int j = 0; j <= 6; j++) {
        float lo, hi;
        unpack2(p0h0[j], lo, hi);
        if (24 - 4 * j < DHALF) acc0[24 - 4 * j] = lo;
        if (23 - 4 * j >= 0)    acc0[23 - 4 * j] = hi;
    }
#pragma unroll
    for (int j = 0; j <= 5; j++) {
        float lo, hi;
        unpack2(p0h1[j], lo, hi);
        acc0[22 - 4 * j] = lo;
        acc0[21 - 4 * j] = hi;
    }
#pragma unroll
    for (int j = 1; j <= 7; j++) {
        float lo, hi;
        unpack2(p1h0[j - 1], lo, hi);
        if (28 - 4 * j < DHALF) acc1[28 - 4 * j] = lo;
        if (27 - 4 * j >= 0)    acc1[27 - 4 * j] = hi;
    }
#pragma unroll
    for (int j = 1; j <= 6; j++) {
        float lo, hi;
        unpack2(p1h1[j - 1], lo, hi);
        acc1[26 - 4 * j] = lo;
        acc1[25 - 4 * j] = hi;
    }

    // out[b, 24g + a, h, w0..w0+1] as float2 (coalesced per a).
    const size_t obase = (((size_t)b * DD + DHALF * g) * HH + h) * WW + w0;
#pragma unroll
    for (int a = 0; a < DHALF; a++) {
        *reinterpret_cast<float2*>(&out[obase + (size_t)a * HH * WW]) =
            make_float2(acc0[a], acc1[a]);
    }
}

extern "C" void kernel_launch(void* const* d_in, const int* in_sizes, int n_in,
                              void* d_out, int out_size) {
    const float* feat_l = (const float*)d_in[0];
    const float* feat_r = (const float*)d_in[1];
    float* out = (float*)d_out;

    dim3 grid(4, HH, BB);   // x = (wt<<1)|g : twin-g CTAs share R rows via L2
    build_volume2d_kernel<<<grid, TPB>>>(feat_l, feat_r, out);
}